// round 1
// baseline (speedup 1.0000x reference)
#include <cuda_runtime.h>

// Problem dims (fixed by the dataset)
#define BD 4096   // batch rows
#define ID 1024   // inner dim
#define PD 512    // prototypes
#define FD 2048   // features
#define K2 (2*FD) // fused K for stage-2 GEMM = 4096

// Scratch (device globals: allocation-free per harness rules)
__device__ float g_A[(size_t)BD * K2];  // [B, 2F]: [u^2 | u]          (64 MB)
__device__ float g_C[(size_t)PD * K2];  // [P, 2F]: [th*v^2+al*v | be*v^2] (8 MB)
__device__ float g_su[BD];              // alpha * ||u_b||^2
__device__ float g_sv[PD];              // beta  * ||v_p||^2

// ---------------------------------------------------------------------------
// Generic NT SGEMM: C[m,n] = sum_k A[m,k]*B[n,k]   (both operands K-contiguous)
// 256 threads, BK=8, (BM/TM)*(BN/TN) must equal 256.
// MODE 0: epilogue writes u^2 and u into g_A        (A=x, B=features)
// MODE 1: epilogue writes th*v^2+al*v and be*v^2 into g_C (A=protos, B=features)
// MODE 2: A=g_A, B=g_C implicitly; out = acc - su[row] - sv[col]
// ---------------------------------------------------------------------------
template<int BM, int BN, int TM, int TN, int MODE>
__global__ __launch_bounds__(256)
void gemm_nt(const float* __restrict__ A, const float* __restrict__ B,
             int K, int lda, int ldb,
             float* __restrict__ out,
             const float* __restrict__ alpha_p,
             const float* __restrict__ beta_p,
             const float* __restrict__ theta_p)
{
    constexpr int BK = 8;
    static_assert((BM/TM)*(BN/TN) == 256, "thread count mismatch");
    __shared__ float As[BK][BM];
    __shared__ float Bs[BK][BN];

    const int t    = threadIdx.x;
    const int tcol = t % (BN / TN);
    const int trow = t / (BN / TN);

    const float* Abase = (MODE == 2) ? (const float*)g_A : A;
    const float* Bbase = (MODE == 2) ? (const float*)g_C : B;

    const float* Ap = Abase + (size_t)(blockIdx.y * BM) * lda;
    const float* Bp = Bbase + (size_t)(blockIdx.x * BN) * ldb;

    float acc[TM][TN];
    #pragma unroll
    for (int i = 0; i < TM; i++)
        #pragma unroll
        for (int j = 0; j < TN; j++) acc[i][j] = 0.0f;

    constexpr int AE = BM * BK / 256;  // scalar loads per thread (A tile)
    constexpr int BE = BN * BK / 256;  // scalar loads per thread (B tile)

    for (int k0 = 0; k0 < K; k0 += BK) {
        #pragma unroll
        for (int i = 0; i < AE; i++) {
            int e = i * 256 + t;
            int m = e >> 3, kk = e & 7;
            As[kk][m] = Ap[(size_t)m * lda + k0 + kk];
        }
        #pragma unroll
        for (int i = 0; i < BE; i++) {
            int e = i * 256 + t;
            int n = e >> 3, kk = e & 7;
            Bs[kk][n] = Bp[(size_t)n * ldb + k0 + kk];
        }
        __syncthreads();

        #pragma unroll
        for (int kk = 0; kk < BK; kk++) {
            float areg[TM], breg[TN];
            #pragma unroll
            for (int i = 0; i < TM; i += 4) {
                float4 v = *reinterpret_cast<const float4*>(&As[kk][trow * TM + i]);
                areg[i] = v.x; areg[i+1] = v.y; areg[i+2] = v.z; areg[i+3] = v.w;
            }
            #pragma unroll
            for (int j = 0; j < TN; j += 4) {
                float4 v = *reinterpret_cast<const float4*>(&Bs[kk][tcol * TN + j]);
                breg[j] = v.x; breg[j+1] = v.y; breg[j+2] = v.z; breg[j+3] = v.w;
            }
            #pragma unroll
            for (int i = 0; i < TM; i++)
                #pragma unroll
                for (int j = 0; j < TN; j++)
                    acc[i][j] = fmaf(areg[i], breg[j], acc[i][j]);
        }
        __syncthreads();
    }

    const int row0 = blockIdx.y * BM + trow * TM;
    const int col0 = blockIdx.x * BN + tcol * TN;

    if (MODE == 0) {
        #pragma unroll
        for (int i = 0; i < TM; i++) {
            float* rowp = g_A + (size_t)(row0 + i) * K2;
            #pragma unroll
            for (int j = 0; j < TN; j++) {
                float u = fmaxf(acc[i][j], 0.0f);
                rowp[col0 + j]      = u * u;
                rowp[FD + col0 + j] = u;
            }
        }
    } else if (MODE == 1) {
        const float al = *alpha_p, be = *beta_p, th = *theta_p;
        #pragma unroll
        for (int i = 0; i < TM; i++) {
            float* rowp = g_C + (size_t)(row0 + i) * K2;
            #pragma unroll
            for (int j = 0; j < TN; j++) {
                float v = fmaxf(acc[i][j], 0.0f);
                rowp[col0 + j]      = fmaf(th * v, v, al * v);  // th*v^2 + al*v
                rowp[FD + col0 + j] = be * v * v;
            }
        }
    } else {
        #pragma unroll
        for (int i = 0; i < TM; i++) {
            const float s_u = g_su[row0 + i];
            #pragma unroll
            for (int j = 0; j < TN; j++)
                out[(size_t)(row0 + i) * PD + (col0 + j)] = acc[i][j] - s_u - g_sv[col0 + j];
        }
    }
}

// su[b] = alpha * sum_f u^2   (first half of g_A row)
__global__ __launch_bounds__(256) void reduce_su(const float* __restrict__ alpha_p)
{
    const int row = blockIdx.x;
    const float* p = g_A + (size_t)row * K2;
    float s = 0.0f;
    for (int c = threadIdx.x; c < FD; c += 256) s += p[c];
    __shared__ float red[256];
    red[threadIdx.x] = s;
    __syncthreads();
    for (int o = 128; o > 0; o >>= 1) {
        if (threadIdx.x < o) red[threadIdx.x] += red[threadIdx.x + o];
        __syncthreads();
    }
    if (threadIdx.x == 0) g_su[row] = red[0] * (*alpha_p);
}

// sv[p] = sum_f (beta*v^2)   (second half of g_C row already carries beta)
__global__ __launch_bounds__(256) void reduce_sv()
{
    const int row = blockIdx.x;
    const float* p = g_C + (size_t)row * K2 + FD;
    float s = 0.0f;
    for (int c = threadIdx.x; c < FD; c += 256) s += p[c];
    __shared__ float red[256];
    red[threadIdx.x] = s;
    __syncthreads();
    for (int o = 128; o > 0; o >>= 1) {
        if (threadIdx.x < o) red[threadIdx.x] += red[threadIdx.x + o];
        __syncthreads();
    }
    if (threadIdx.x == 0) g_sv[row] = red[0];
}

extern "C" void kernel_launch(void* const* d_in, const int* in_sizes, int n_in,
                              void* d_out, int out_size)
{
    const float* x      = (const float*)d_in[0];  // [4096, 1024]
    const float* feats  = (const float*)d_in[1];  // [2048, 1024]
    const float* protos = (const float*)d_in[2];  // [512, 1024]
    const float* alpha  = (const float*)d_in[3];
    const float* beta   = (const float*)d_in[4];
    const float* theta  = (const float*)d_in[5];
    float* out = (float*)d_out;                   // [4096, 512] fp32

    dim3 blk(256);

    // Stage 1a: xf GEMM -> g_A = [u^2 | u]
    gemm_nt<128,128,8,8,0><<<dim3(FD/128, BD/128), blk>>>(
        x, feats, ID, ID, ID, nullptr, alpha, beta, theta);

    // Stage 1b: pf GEMM -> g_C = [th*v^2+al*v | be*v^2]
    gemm_nt<128,128,8,8,1><<<dim3(FD/128, PD/128), blk>>>(
        protos, feats, ID, ID, ID, nullptr, alpha, beta, theta);

    // Row-sum corrections
    reduce_su<<<BD, blk>>>(alpha);
    reduce_sv<<<PD, blk>>>();

    // Stage 2: fused output GEMM (K = 2F = 4096), epilogue subtracts corrections
    gemm_nt<128,64,8,4,2><<<dim3(PD/64, BD/128), blk>>>(
        nullptr, nullptr, K2, K2, K2, out, nullptr, nullptr, nullptr);
}

// round 6
// speedup vs baseline: 3.6045x; 3.6045x over previous
#include <cuda_runtime.h>
#include <cuda_bf16.h>
#include <cstdint>

#define BD 4096
#define ID 1024
#define PD 512
#define FD 2048
#define K2 4096

#define SMEM_SZ 65536   // 2 buffers x (16KB A + 16KB B)

// ---------------- scratch (device globals; allocation-free) ----------------
__device__ __align__(256) __nv_bfloat16 g_xh[(size_t)BD*ID];
__device__ __align__(256) __nv_bfloat16 g_xl[(size_t)BD*ID];
__device__ __align__(256) __nv_bfloat16 g_fh[(size_t)FD*ID];
__device__ __align__(256) __nv_bfloat16 g_fl[(size_t)FD*ID];
__device__ __align__(256) __nv_bfloat16 g_ph[(size_t)PD*ID];
__device__ __align__(256) __nv_bfloat16 g_pl[(size_t)PD*ID];
__device__ __align__(256) __nv_bfloat16 g_Ah[(size_t)BD*K2];  // [u^2 | u] hi
__device__ __align__(256) __nv_bfloat16 g_Al[(size_t)BD*K2];  // lo
__device__ __align__(256) __nv_bfloat16 g_Ch[(size_t)PD*K2];  // [th*v^2+al*v | be*v^2] hi
__device__ __align__(256) __nv_bfloat16 g_Cl[(size_t)PD*K2];  // lo
__device__ float g_su[BD];   // alpha * sum_f u^2
__device__ float g_sv[PD];   // sum_f be*v^2

// ---------------- PTX helpers (sm_80-era: valid on plain sm_103 target) ----
__device__ __forceinline__ uint32_t smem_u32(const void* p) {
    uint32_t a;
    asm("{ .reg .u64 t; cvta.to.shared.u64 t, %1; cvt.u32.u64 %0, t; }" : "=r"(a) : "l"(p));
    return a;
}
__device__ __forceinline__ void cp16(uint32_t dst, const void* src) {
    asm volatile("cp.async.cg.shared.global [%0], [%1], 16;" :: "r"(dst), "l"(src));
}
__device__ __forceinline__ void cp_commit() { asm volatile("cp.async.commit_group;" ::: "memory"); }
template<int N> __device__ __forceinline__ void cp_wait() {
    asm volatile("cp.async.wait_group %0;" :: "n"(N) : "memory");
}
__device__ __forceinline__ void ldsm4(uint32_t (&r)[4], uint32_t addr) {
    asm volatile("ldmatrix.sync.aligned.m8n8.x4.shared.b16 {%0,%1,%2,%3}, [%4];"
        : "=r"(r[0]), "=r"(r[1]), "=r"(r[2]), "=r"(r[3]) : "r"(addr));
}
__device__ __forceinline__ void mma16816(float* d, const uint32_t* a, uint32_t b0, uint32_t b1) {
    asm volatile("mma.sync.aligned.m16n8k16.row.col.f32.bf16.bf16.f32 "
        "{%0,%1,%2,%3}, {%4,%5,%6,%7}, {%8,%9}, {%0,%1,%2,%3};"
        : "+f"(d[0]), "+f"(d[1]), "+f"(d[2]), "+f"(d[3])
        : "r"(a[0]), "r"(a[1]), "r"(a[2]), "r"(a[3]), "r"(b0), "r"(b1));
}

// ---------------- split conversion ----------------
__global__ __launch_bounds__(256) void split_all(const float* __restrict__ x,
                                                 const float* __restrict__ f,
                                                 const float* __restrict__ p)
{
    const int i = blockIdx.x * 256 + threadIdx.x;
    constexpr int N1 = BD * ID;
    constexpr int N2 = N1 + FD * ID;
    float v; __nv_bfloat16 *hp, *lp; int j;
    if (i < N1)      { j = i;      v = x[j]; hp = g_xh; lp = g_xl; }
    else if (i < N2) { j = i - N1; v = f[j]; hp = g_fh; lp = g_fl; }
    else             { j = i - N2; v = p[j]; hp = g_ph; lp = g_pl; }
    __nv_bfloat16 h = __float2bfloat16(v);
    hp[j] = h;
    lp[j] = __float2bfloat16(v - __bfloat162float(h));
}

__device__ __forceinline__ void split2(float a, float b, __nv_bfloat162& h, __nv_bfloat162& l) {
    __nv_bfloat16 ha = __float2bfloat16(a);
    __nv_bfloat16 hb = __float2bfloat16(b);
    h.x = ha; h.y = hb;
    l.x = __float2bfloat16(a - __bfloat162float(ha));
    l.y = __float2bfloat16(b - __bfloat162float(hb));
}

// ---------------------------------------------------------------------------
// 128x128xBK64 bf16 mma.sync GEMM (NT), 3 split passes (hh, h*Bl, Al*Bh).
// smem tiles: 128 rows x 64 bf16 (128B rows), chunk swizzle c^=(r&7).
// MODE 0: x @ f^T    -> relu -> g_A split [u^2 | u]
// MODE 1: p @ f^T    -> relu -> g_C split [th v^2 + al v | be v^2]
// MODE 2: A' @ C'^T  -> out = acc - su[row] - sv[col]
// ---------------------------------------------------------------------------
template<int MODE>
__global__ void __launch_bounds__(256)
tv_gemm(float* __restrict__ out,
        const float* __restrict__ alpha_p,
        const float* __restrict__ beta_p,
        const float* __restrict__ theta_p)
{
    constexpr int K  = (MODE == 2) ? K2 : ID;
    constexpr int KT = K / 64;
    constexpr int T  = 3 * KT;

    extern __shared__ __align__(1024) char smem[];
    const uint32_t sb = smem_u32(smem);
    const int tid  = threadIdx.x;
    const int lane = tid & 31, wid = tid >> 5;
    const int wm = wid >> 2, wn = wid & 3;          // 2 x 4 warp grid

    const __nv_bfloat16 *Ahi, *Alo, *Bhi, *Blo;
    if constexpr (MODE == 0)      { Ahi = g_xh; Alo = g_xl; Bhi = g_fh; Blo = g_fl; }
    else if constexpr (MODE == 1) { Ahi = g_ph; Alo = g_pl; Bhi = g_fh; Blo = g_fl; }
    else                          { Ahi = g_Ah; Alo = g_Al; Bhi = g_Ch; Blo = g_Cl; }
    const size_t aoff = (size_t)blockIdx.y * 128 * K;
    const size_t boff = (size_t)blockIdx.x * 128 * K;
    Ahi += aoff; Alo += aoff; Bhi += boff; Blo += boff;

    float acc[4][4][4];
    #pragma unroll
    for (int a = 0; a < 4; a++)
        #pragma unroll
        for (int b = 0; b < 4; b++)
            #pragma unroll
            for (int c = 0; c < 4; c++) acc[a][b][c] = 0.0f;

    auto load_tiles = [&](int i) {
        const int p  = i / KT;
        const int k0 = (i - p * KT) << 6;
        const __nv_bfloat16* As = (p == 2) ? Alo : Ahi;
        const __nv_bfloat16* Bs = (p == 1) ? Blo : Bhi;
        const uint32_t base = sb + (i & 1) * 32768;
        #pragma unroll
        for (int it = 0; it < 4; it++) {
            const int idx = (it << 8) + tid;          // 0..1023 chunk ids
            const int r = idx >> 3, c = idx & 7;
            const uint32_t sw = (uint32_t)((c ^ (r & 7)) << 4);
            cp16(base + r * 128 + sw,         As + (size_t)r * K + k0 + (c << 3));
            cp16(base + 16384 + r * 128 + sw, Bs + (size_t)r * K + k0 + (c << 3));
        }
    };

    load_tiles(0); cp_commit();

    for (int i = 0; i < T; i++) {
        if (i + 1 < T) { load_tiles(i + 1); cp_commit(); cp_wait<1>(); }
        else           { cp_wait<0>(); }
        __syncthreads();

        const uint32_t Ab = sb + (i & 1) * 32768;
        const uint32_t Bb = Ab + 16384;

        #pragma unroll
        for (int ks = 0; ks < 4; ks++) {
            uint32_t afr[4][4], bfr[2][4];
            #pragma unroll
            for (int mt = 0; mt < 4; mt++) {
                const int r  = wm * 64 + mt * 16 + (lane & 15);
                const int cb = (ks << 1) + (lane >> 4);
                ldsm4(afr[mt], Ab + r * 128 + ((cb ^ (r & 7)) << 4));
            }
            #pragma unroll
            for (int np = 0; np < 2; np++) {
                const int g  = lane >> 3;
                const int r  = wn * 32 + np * 16 + ((g & 2) << 2) + (lane & 7);
                const int cb = (ks << 1) + (g & 1);
                ldsm4(bfr[np], Bb + r * 128 + ((cb ^ (r & 7)) << 4));
            }
            #pragma unroll
            for (int mt = 0; mt < 4; mt++)
                #pragma unroll
                for (int nt = 0; nt < 4; nt++)
                    mma16816(acc[mt][nt], afr[mt],
                             bfr[nt >> 1][(nt & 1) * 2], bfr[nt >> 1][(nt & 1) * 2 + 1]);
        }
        __syncthreads();
    }

    // ---------------- epilogue ----------------
    if constexpr (MODE == 2) {
        #pragma unroll
        for (int mt = 0; mt < 4; mt++) {
            const size_t r1 = (size_t)blockIdx.y * 128 + wm * 64 + mt * 16 + (lane >> 2);
            const size_t r2 = r1 + 8;
            const float s1 = g_su[r1], s2 = g_su[r2];
            #pragma unroll
            for (int nt = 0; nt < 4; nt++) {
                const int c = blockIdx.x * 128 + wn * 32 + nt * 8 + ((lane & 3) << 1);
                const float sv0 = g_sv[c], sv1 = g_sv[c + 1];
                const float* d = acc[mt][nt];
                float2 o1 = make_float2(d[0] - s1 - sv0, d[1] - s1 - sv1);
                float2 o2 = make_float2(d[2] - s2 - sv0, d[3] - s2 - sv1);
                *reinterpret_cast<float2*>(&out[r1 * PD + c]) = o1;
                *reinterpret_cast<float2*>(&out[r2 * PD + c]) = o2;
            }
        }
    } else {
        float al = 0.f, be = 0.f, th = 0.f;
        if constexpr (MODE == 1) { al = *alpha_p; be = *beta_p; th = *theta_p; }

        #pragma unroll
        for (int mt = 0; mt < 4; mt++) {
            const size_t rr[2] = {
                (size_t)blockIdx.y * 128 + wm * 64 + mt * 16 + (lane >> 2),
                (size_t)blockIdx.y * 128 + wm * 64 + mt * 16 + (lane >> 2) + 8 };
            #pragma unroll
            for (int nt = 0; nt < 4; nt++) {
                const int c = blockIdx.x * 128 + wn * 32 + nt * 8 + ((lane & 3) << 1);
                #pragma unroll
                for (int h = 0; h < 2; h++) {
                    const float v0 = fmaxf(acc[mt][nt][h * 2 + 0], 0.0f);
                    const float v1 = fmaxf(acc[mt][nt][h * 2 + 1], 0.0f);
                    const size_t rb = rr[h] * (size_t)K2;
                    __nv_bfloat162 hh, ll;
                    if constexpr (MODE == 0) {
                        split2(v0 * v0, v1 * v1, hh, ll);
                        *reinterpret_cast<__nv_bfloat162*>(&g_Ah[rb + c]) = hh;
                        *reinterpret_cast<__nv_bfloat162*>(&g_Al[rb + c]) = ll;
                        split2(v0, v1, hh, ll);
                        *reinterpret_cast<__nv_bfloat162*>(&g_Ah[rb + FD + c]) = hh;
                        *reinterpret_cast<__nv_bfloat162*>(&g_Al[rb + FD + c]) = ll;
                    } else {
                        split2(fmaf(th * v0, v0, al * v0), fmaf(th * v1, v1, al * v1), hh, ll);
                        *reinterpret_cast<__nv_bfloat162*>(&g_Ch[rb + c]) = hh;
                        *reinterpret_cast<__nv_bfloat162*>(&g_Cl[rb + c]) = ll;
                        split2(be * v0 * v0, be * v1 * v1, hh, ll);
                        *reinterpret_cast<__nv_bfloat162*>(&g_Ch[rb + FD + c]) = hh;
                        *reinterpret_cast<__nv_bfloat162*>(&g_Cl[rb + FD + c]) = ll;
                    }
                }
            }
        }
    }
}

// su[b] = alpha * sum_f u^2 (hi+lo halves of g_A first FD cols)
__global__ __launch_bounds__(256) void reduce_su(const float* __restrict__ alpha_p)
{
    const int row = blockIdx.x, tid = threadIdx.x;
    const __nv_bfloat162* ph = reinterpret_cast<const __nv_bfloat162*>(g_Ah + (size_t)row * K2);
    const __nv_bfloat162* pl = reinterpret_cast<const __nv_bfloat162*>(g_Al + (size_t)row * K2);
    float s = 0.0f;
    for (int c = tid; c < FD / 2; c += 256) {
        float2 h = __bfloat1622float2(ph[c]);
        float2 l = __bfloat1622float2(pl[c]);
        s += (h.x + l.x) + (h.y + l.y);
    }
    __shared__ float red[256];
    red[tid] = s; __syncthreads();
    for (int o = 128; o > 0; o >>= 1) {
        if (tid < o) red[tid] += red[tid + o];
        __syncthreads();
    }
    if (tid == 0) g_su[row] = red[0] * (*alpha_p);
}

// sv[p] = sum_f be*v^2 (hi+lo halves of g_C second FD cols; beta already folded)
__global__ __launch_bounds__(256) void reduce_sv()
{
    const int row = blockIdx.x, tid = threadIdx.x;
    const __nv_bfloat162* ph = reinterpret_cast<const __nv_bfloat162*>(g_Ch + (size_t)row * K2 + FD);
    const __nv_bfloat162* pl = reinterpret_cast<const __nv_bfloat162*>(g_Cl + (size_t)row * K2 + FD);
    float s = 0.0f;
    for (int c = tid; c < FD / 2; c += 256) {
        float2 h = __bfloat1622float2(ph[c]);
        float2 l = __bfloat1622float2(pl[c]);
        s += (h.x + l.x) + (h.y + l.y);
    }
    __shared__ float red[256];
    red[tid] = s; __syncthreads();
    for (int o = 128; o > 0; o >>= 1) {
        if (tid < o) red[tid] += red[tid + o];
        __syncthreads();
    }
    if (tid == 0) g_sv[row] = red[0];
}

// ---------------------------------------------------------------------------
extern "C" void kernel_launch(void* const* d_in, const int* in_sizes, int n_in,
                              void* d_out, int out_size)
{
    const float* x      = (const float*)d_in[0];  // [4096, 1024]
    const float* feats  = (const float*)d_in[1];  // [2048, 1024]
    const float* protos = (const float*)d_in[2];  // [512, 1024]
    const float* alpha  = (const float*)d_in[3];
    const float* beta   = (const float*)d_in[4];
    const float* theta  = (const float*)d_in[5];
    float* out = (float*)d_out;                   // [4096, 512]

    cudaFuncSetAttribute(tv_gemm<0>, cudaFuncAttributeMaxDynamicSharedMemorySize, SMEM_SZ);
    cudaFuncSetAttribute(tv_gemm<1>, cudaFuncAttributeMaxDynamicSharedMemorySize, SMEM_SZ);
    cudaFuncSetAttribute(tv_gemm<2>, cudaFuncAttributeMaxDynamicSharedMemorySize, SMEM_SZ);

    constexpr int NTOT = BD * ID + FD * ID + PD * ID;
    split_all<<<NTOT / 256, 256>>>(x, feats, protos);

    tv_gemm<0><<<dim3(FD / 128, BD / 128), 256, SMEM_SZ>>>(nullptr, alpha, beta, theta);
    tv_gemm<1><<<dim3(FD / 128, PD / 128), 256, SMEM_SZ>>>(nullptr, alpha, beta, theta);

    reduce_su<<<BD, 256>>>(alpha);
    reduce_sv<<<PD, 256>>>();

    tv_gemm<2><<<dim3(PD / 128, BD / 128), 256, SMEM_SZ>>>(out, alpha, beta, theta);
}

// round 7
// speedup vs baseline: 4.4558x; 1.2362x over previous
#include <cuda_runtime.h>
#include <cuda_bf16.h>
#include <cstdint>

#define BD 4096
#define ID 1024
#define PD 512
#define FD 2048
#define K2 4096

#define SMEM12 (3 * 32768)   // 3-stage x (16KB A + 16KB B)
#define SMEM3  (3 * 24576)   // 3-stage x (16KB A + 8KB B)

// ---------------- scratch (device globals; allocation-free) ----------------
__device__ __align__(256) __nv_bfloat16 g_xh[(size_t)BD*ID];
__device__ __align__(256) __nv_bfloat16 g_xl[(size_t)BD*ID];
__device__ __align__(256) __nv_bfloat16 g_fh[(size_t)FD*ID];
__device__ __align__(256) __nv_bfloat16 g_fl[(size_t)FD*ID];
__device__ __align__(256) __nv_bfloat16 g_ph[(size_t)PD*ID];
__device__ __align__(256) __nv_bfloat16 g_pl[(size_t)PD*ID];
__device__ __align__(256) __nv_bfloat16 g_Ah[(size_t)BD*K2];  // [u^2 | u] hi
__device__ __align__(256) __nv_bfloat16 g_Al[(size_t)BD*K2];  // lo
__device__ __align__(256) __nv_bfloat16 g_Ch[(size_t)PD*K2];  // [th*v^2+al*v | be*v^2] hi
__device__ __align__(256) __nv_bfloat16 g_Cl[(size_t)PD*K2];  // lo
__device__ float g_su[BD];   // raw sum_f u^2
__device__ float g_sv[PD];   // raw sum_f v^2

// ---------------- PTX helpers ----------------
__device__ __forceinline__ uint32_t smem_u32(const void* p) {
    uint32_t a;
    asm("{ .reg .u64 t; cvta.to.shared.u64 t, %1; cvt.u32.u64 %0, t; }" : "=r"(a) : "l"(p));
    return a;
}
__device__ __forceinline__ void cp16(uint32_t dst, const void* src) {
    asm volatile("cp.async.cg.shared.global [%0], [%1], 16;" :: "r"(dst), "l"(src));
}
__device__ __forceinline__ void cp_commit() { asm volatile("cp.async.commit_group;" ::: "memory"); }
template<int N> __device__ __forceinline__ void cp_wait() {
    asm volatile("cp.async.wait_group %0;" :: "n"(N) : "memory");
}
__device__ __forceinline__ void ldsm4(uint32_t (&r)[4], uint32_t addr) {
    asm volatile("ldmatrix.sync.aligned.m8n8.x4.shared.b16 {%0,%1,%2,%3}, [%4];"
        : "=r"(r[0]), "=r"(r[1]), "=r"(r[2]), "=r"(r[3]) : "r"(addr));
}
__device__ __forceinline__ void mma16816(float* d, const uint32_t* a, uint32_t b0, uint32_t b1) {
    asm volatile("mma.sync.aligned.m16n8k16.row.col.f32.bf16.bf16.f32 "
        "{%0,%1,%2,%3}, {%4,%5,%6,%7}, {%8,%9}, {%0,%1,%2,%3};"
        : "+f"(d[0]), "+f"(d[1]), "+f"(d[2]), "+f"(d[3])
        : "r"(a[0]), "r"(a[1]), "r"(a[2]), "r"(a[3]), "r"(b0), "r"(b1));
}

// ---------------- split conversion + accumulator zero ----------------
__global__ __launch_bounds__(256) void split_all(const float* __restrict__ x,
                                                 const float* __restrict__ f,
                                                 const float* __restrict__ p)
{
    const int i = blockIdx.x * 256 + threadIdx.x;
    constexpr int N1 = BD * ID;
    constexpr int N2 = N1 + FD * ID;
    float v; __nv_bfloat16 *hp, *lp; int j;
    if (i < N1)      { j = i;      v = x[j]; hp = g_xh; lp = g_xl; }
    else if (i < N2) { j = i - N1; v = f[j]; hp = g_fh; lp = g_fl; }
    else             { j = i - N2; v = p[j]; hp = g_ph; lp = g_pl; }
    __nv_bfloat16 h = __float2bfloat16(v);
    hp[j] = h;
    lp[j] = __float2bfloat16(v - __bfloat162float(h));
    if (i < BD) g_su[i] = 0.0f;
    if (i < PD) g_sv[i] = 0.0f;
}

__device__ __forceinline__ void split2(float a, float b, __nv_bfloat162& h, __nv_bfloat162& l) {
    __nv_bfloat16 ha = __float2bfloat16(a);
    __nv_bfloat16 hb = __float2bfloat16(b);
    h.x = ha; h.y = hb;
    l.x = __float2bfloat16(a - __bfloat162float(ha));
    l.y = __float2bfloat16(b - __bfloat162float(hb));
}

// ---------------------------------------------------------------------------
// Fused GEMM1+GEMM2: 128x128xBK64 bf16 mma.sync (NT), 3 split passes, K=1024.
// bid <  512 : MODE0  x @ f^T -> relu -> g_A split [u^2|u], atomic sum u^2
// bid >= 512 : MODE1  p @ f^T -> relu -> g_C split [th v^2+al v | be v^2], atomic sum v^2
// 3-stage cp.async pipeline, 2 CTAs/SM via launch_bounds.
// ---------------------------------------------------------------------------
__global__ void __launch_bounds__(256, 2)
tv_gemm12(const float* __restrict__ alpha_p,
          const float* __restrict__ beta_p,
          const float* __restrict__ theta_p)
{
    constexpr int K  = ID;
    constexpr int KT = K / 64;
    constexpr int T  = 3 * KT;

    extern __shared__ __align__(1024) char smem[];
    const uint32_t sb = smem_u32(smem);
    const int tid  = threadIdx.x;
    const int lane = tid & 31, wid = tid >> 5;
    const int wm = wid >> 2, wn = wid & 3;          // 2 x 4 warp grid

    const int bid   = blockIdx.x;
    const int mode1 = (bid >= 512);
    const int lbid  = mode1 ? bid - 512 : bid;
    const int bx    = lbid & 15;
    const int by    = lbid >> 4;

    const __nv_bfloat16* Ahi = (mode1 ? g_ph : g_xh) + (size_t)by * 128 * K;
    const __nv_bfloat16* Alo = (mode1 ? g_pl : g_xl) + (size_t)by * 128 * K;
    const __nv_bfloat16* Bhi = g_fh + (size_t)bx * 128 * K;
    const __nv_bfloat16* Blo = g_fl + (size_t)bx * 128 * K;

    float acc[4][4][4];
    #pragma unroll
    for (int a = 0; a < 4; a++)
        #pragma unroll
        for (int b = 0; b < 4; b++)
            #pragma unroll
            for (int c = 0; c < 4; c++) acc[a][b][c] = 0.0f;

    auto load_tiles = [&](int i) {
        const int p  = i / KT;
        const int k0 = (i - p * KT) << 6;
        const __nv_bfloat16* As = (p == 2) ? Alo : Ahi;
        const __nv_bfloat16* Bs = (p == 1) ? Blo : Bhi;
        const uint32_t base = sb + (i % 3) * 32768;
        #pragma unroll
        for (int it = 0; it < 4; it++) {
            const int idx = (it << 8) + tid;          // 0..1023
            const int r = idx >> 3, c = idx & 7;
            const uint32_t sw = (uint32_t)((c ^ (r & 7)) << 4);
            cp16(base + r * 128 + sw,         As + (size_t)r * K + k0 + (c << 3));
            cp16(base + 16384 + r * 128 + sw, Bs + (size_t)r * K + k0 + (c << 3));
        }
    };

    load_tiles(0); cp_commit();
    load_tiles(1); cp_commit();

    for (int i = 0; i < T; i++) {
        if (i + 2 < T)      { load_tiles(i + 2); cp_commit(); cp_wait<2>(); }
        else if (i + 1 < T) { cp_wait<1>(); }
        else                { cp_wait<0>(); }
        __syncthreads();

        const uint32_t Ab = sb + (i % 3) * 32768;
        const uint32_t Bb = Ab + 16384;

        #pragma unroll
        for (int ks = 0; ks < 4; ks++) {
            uint32_t afr[4][4], bfr[2][4];
            #pragma unroll
            for (int mt = 0; mt < 4; mt++) {
                const int r  = wm * 64 + mt * 16 + (lane & 15);
                const int cb = (ks << 1) + (lane >> 4);
                ldsm4(afr[mt], Ab + r * 128 + ((cb ^ (r & 7)) << 4));
            }
            #pragma unroll
            for (int np = 0; np < 2; np++) {
                const int g  = lane >> 3;
                const int r  = wn * 32 + np * 16 + ((g & 2) << 2) + (lane & 7);
                const int cb = (ks << 1) + (g & 1);
                ldsm4(bfr[np], Bb + r * 128 + ((cb ^ (r & 7)) << 4));
            }
            #pragma unroll
            for (int mt = 0; mt < 4; mt++)
                #pragma unroll
                for (int nt = 0; nt < 4; nt++)
                    mma16816(acc[mt][nt], afr[mt],
                             bfr[nt >> 1][(nt & 1) * 2], bfr[nt >> 1][(nt & 1) * 2 + 1]);
        }
        __syncthreads();
    }

    // ---------------- epilogue: split-store + fused row-sum atomics --------
    float al = 0.f, be = 0.f, th = 0.f;
    if (mode1) { al = *alpha_p; be = *beta_p; th = *theta_p; }

    float rs[4][2];
    #pragma unroll
    for (int mt = 0; mt < 4; mt++) { rs[mt][0] = 0.0f; rs[mt][1] = 0.0f; }

    #pragma unroll
    for (int mt = 0; mt < 4; mt++) {
        const size_t rbase = (size_t)by * 128 + wm * 64 + mt * 16 + (lane >> 2);
        #pragma unroll
        for (int nt = 0; nt < 4; nt++) {
            const int c = bx * 128 + wn * 32 + nt * 8 + ((lane & 3) << 1);
            #pragma unroll
            for (int h = 0; h < 2; h++) {
                const float v0 = fmaxf(acc[mt][nt][h * 2 + 0], 0.0f);
                const float v1 = fmaxf(acc[mt][nt][h * 2 + 1], 0.0f);
                const float q0 = v0 * v0, q1 = v1 * v1;
                rs[mt][h] += q0 + q1;
                const size_t rb = (rbase + h * 8) * (size_t)K2;
                __nv_bfloat162 hh, ll;
                if (!mode1) {
                    split2(q0, q1, hh, ll);
                    *reinterpret_cast<__nv_bfloat162*>(&g_Ah[rb + c]) = hh;
                    *reinterpret_cast<__nv_bfloat162*>(&g_Al[rb + c]) = ll;
                    split2(v0, v1, hh, ll);
                    *reinterpret_cast<__nv_bfloat162*>(&g_Ah[rb + FD + c]) = hh;
                    *reinterpret_cast<__nv_bfloat162*>(&g_Al[rb + FD + c]) = ll;
                } else {
                    split2(fmaf(th, q0, al * v0), fmaf(th, q1, al * v1), hh, ll);
                    *reinterpret_cast<__nv_bfloat162*>(&g_Ch[rb + c]) = hh;
                    *reinterpret_cast<__nv_bfloat162*>(&g_Cl[rb + c]) = ll;
                    split2(be * q0, be * q1, hh, ll);
                    *reinterpret_cast<__nv_bfloat162*>(&g_Ch[rb + FD + c]) = hh;
                    *reinterpret_cast<__nv_bfloat162*>(&g_Cl[rb + FD + c]) = ll;
                }
            }
        }
    }

    // quad reduce (lanes with same lane>>2 hold same row) then one atomic
    float* sums = mode1 ? g_sv : g_su;
    #pragma unroll
    for (int mt = 0; mt < 4; mt++)
        #pragma unroll
        for (int h = 0; h < 2; h++) {
            float v = rs[mt][h];
            v += __shfl_xor_sync(0xffffffffu, v, 1);
            v += __shfl_xor_sync(0xffffffffu, v, 2);
            if ((lane & 3) == 0) {
                const int row = by * 128 + wm * 64 + mt * 16 + (lane >> 2) + h * 8;
                atomicAdd(&sums[row], v);
            }
        }
}

// ---------------------------------------------------------------------------
// GEMM3: 128(M) x 64(N) x BK64, K=4096, 3 passes. 256 CTAs, all co-resident.
// out = acc - alpha*su[row] - beta*sv[col]
// ---------------------------------------------------------------------------
__global__ void __launch_bounds__(256, 2)
tv_gemm3(float* __restrict__ out,
         const float* __restrict__ alpha_p,
         const float* __restrict__ beta_p)
{
    constexpr int K  = K2;
    constexpr int KT = K / 64;
    constexpr int T  = 3 * KT;

    extern __shared__ __align__(1024) char smem[];
    const uint32_t sb = smem_u32(smem);
    const int tid  = threadIdx.x;
    const int lane = tid & 31, wid = tid >> 5;
    const int wm = wid >> 1, wn = wid & 1;          // 4 x 2 warp grid, warp tile 32x32

    const int bx = blockIdx.x;                      // 8 N-tiles
    const int by = blockIdx.y;                      // 32 M-tiles

    const __nv_bfloat16* Ahi = g_Ah + (size_t)by * 128 * K;
    const __nv_bfloat16* Alo = g_Al + (size_t)by * 128 * K;
    const __nv_bfloat16* Bhi = g_Ch + (size_t)bx * 64 * K;
    const __nv_bfloat16* Blo = g_Cl + (size_t)bx * 64 * K;

    float acc[2][4][4];
    #pragma unroll
    for (int a = 0; a < 2; a++)
        #pragma unroll
        for (int b = 0; b < 4; b++)
            #pragma unroll
            for (int c = 0; c < 4; c++) acc[a][b][c] = 0.0f;

    auto load_tiles = [&](int i) {
        const int p  = i / KT;
        const int k0 = (i - p * KT) << 6;
        const __nv_bfloat16* As = (p == 2) ? Alo : Ahi;
        const __nv_bfloat16* Bs = (p == 1) ? Blo : Bhi;
        const uint32_t base = sb + (i % 3) * 24576;
        #pragma unroll
        for (int it = 0; it < 4; it++) {           // A: 1024 chunks
            const int idx = (it << 8) + tid;
            const int r = idx >> 3, c = idx & 7;
            const uint32_t sw = (uint32_t)((c ^ (r & 7)) << 4);
            cp16(base + r * 128 + sw, As + (size_t)r * K + k0 + (c << 3));
        }
        #pragma unroll
        for (int it = 0; it < 2; it++) {           // B: 512 chunks
            const int idx = (it << 8) + tid;
            const int r = idx >> 3, c = idx & 7;
            const uint32_t sw = (uint32_t)((c ^ (r & 7)) << 4);
            cp16(base + 16384 + r * 128 + sw, Bs + (size_t)r * K + k0 + (c << 3));
        }
    };

    load_tiles(0); cp_commit();
    load_tiles(1); cp_commit();

    for (int i = 0; i < T; i++) {
        if (i + 2 < T)      { load_tiles(i + 2); cp_commit(); cp_wait<2>(); }
        else if (i + 1 < T) { cp_wait<1>(); }
        else                { cp_wait<0>(); }
        __syncthreads();

        const uint32_t Ab = sb + (i % 3) * 24576;
        const uint32_t Bb = Ab + 16384;

        #pragma unroll
        for (int ks = 0; ks < 4; ks++) {
            uint32_t afr[2][4], bfr[2][4];
            #pragma unroll
            for (int mt = 0; mt < 2; mt++) {
                const int r  = wm * 32 + mt * 16 + (lane & 15);
                const int cb = (ks << 1) + (lane >> 4);
                ldsm4(afr[mt], Ab + r * 128 + ((cb ^ (r & 7)) << 4));
            }
            #pragma unroll
            for (int np = 0; np < 2; np++) {
                const int g  = lane >> 3;
                const int r  = wn * 32 + np * 16 + ((g & 2) << 2) + (lane & 7);
                const int cb = (ks << 1) + (g & 1);
                ldsm4(bfr[np], Bb + r * 128 + ((cb ^ (r & 7)) << 4));
            }
            #pragma unroll
            for (int mt = 0; mt < 2; mt++)
                #pragma unroll
                for (int nt = 0; nt < 4; nt++)
                    mma16816(acc[mt][nt], afr[mt],
                             bfr[nt >> 1][(nt & 1) * 2], bfr[nt >> 1][(nt & 1) * 2 + 1]);
        }
        __syncthreads();
    }

    const float al = *alpha_p, be = *beta_p;

    #pragma unroll
    for (int mt = 0; mt < 2; mt++) {
        const size_t r1 = (size_t)by * 128 + wm * 32 + mt * 16 + (lane >> 2);
        const size_t r2 = r1 + 8;
        const float s1 = al * g_su[r1], s2 = al * g_su[r2];
        #pragma unroll
        for (int nt = 0; nt < 4; nt++) {
            const int c = bx * 64 + wn * 32 + nt * 8 + ((lane & 3) << 1);
            const float sv0 = be * g_sv[c], sv1 = be * g_sv[c + 1];
            const float* d = acc[mt][nt];
            float2 o1 = make_float2(d[0] - s1 - sv0, d[1] - s1 - sv1);
            float2 o2 = make_float2(d[2] - s2 - sv0, d[3] - s2 - sv1);
            *reinterpret_cast<float2*>(&out[r1 * PD + c]) = o1;
            *reinterpret_cast<float2*>(&out[r2 * PD + c]) = o2;
        }
    }
}

// ---------------------------------------------------------------------------
extern "C" void kernel_launch(void* const* d_in, const int* in_sizes, int n_in,
                              void* d_out, int out_size)
{
    const float* x      = (const float*)d_in[0];  // [4096, 1024]
    const float* feats  = (const float*)d_in[1];  // [2048, 1024]
    const float* protos = (const float*)d_in[2];  // [512, 1024]
    const float* alpha  = (const float*)d_in[3];
    const float* beta   = (const float*)d_in[4];
    const float* theta  = (const float*)d_in[5];
    float* out = (float*)d_out;                   // [4096, 512]

    cudaFuncSetAttribute(tv_gemm12, cudaFuncAttributeMaxDynamicSharedMemorySize, SMEM12);
    cudaFuncSetAttribute(tv_gemm3,  cudaFuncAttributeMaxDynamicSharedMemorySize, SMEM3);

    constexpr int NTOT = BD * ID + FD * ID + PD * ID;
    split_all<<<NTOT / 256, 256>>>(x, feats, protos);

    // GEMM1 (512 CTAs) + GEMM2 (64 CTAs) in one launch; epilogues fold row sums
    tv_gemm12<<<576, 256, SMEM12>>>(alpha, beta, theta);

    // Output GEMM: 8 x 32 = 256 CTAs, corrections fused in epilogue
    tv_gemm3<<<dim3(8, 32), 256, SMEM3>>>(out, alpha, beta);
}